// round 1
// baseline (speedup 1.0000x reference)
#include <cuda_runtime.h>

#define BB 512
#define TT 1024
#define IDIM 64
#define HH 10
#define G4 40   // 4*H

// Scratch (static device globals — no runtime allocation)
__device__ float d_XG[BB * TT * G4];   // gate pre-activations (reused by both layers)
__device__ float d_Y1[BB * TT * HH];   // layer-1 hidden outputs
__device__ float d_h1T[BB * HH];
__device__ float d_c1T[BB * HH];

__device__ __forceinline__ float fsigmoid(float x) {
    // safe at both tails: x->-inf => 1/(1+inf)=0 ; x->+inf => 1/(1+0)=1
    return __fdividef(1.0f, 1.0f + __expf(-x));
}
__device__ __forceinline__ float ftanh_(float x) {
    // tanh(x) = 2*sigmoid(2x) - 1 (tail-safe)
    return 2.0f * fsigmoid(2.0f * x) - 1.0f;
}

// ---------------------------------------------------------------------------
// K1: xg1[row, g] = sum_k x[row,k]*Wih1[g,k] + (bih1[g]+bhh1[g]);  row = b*T+t
// ---------------------------------------------------------------------------
__global__ __launch_bounds__(256) void k_inputgemm(
    const float* __restrict__ x,      // [B*T, 64]
    const float* __restrict__ W,      // [40, 64]
    const float* __restrict__ b1,
    const float* __restrict__ b2)
{
    __shared__ float4 sW[G4 * 16];
    __shared__ float  sB[G4];
    int tid = threadIdx.x;
    for (int i = tid; i < G4 * 16; i += blockDim.x)
        sW[i] = reinterpret_cast<const float4*>(W)[i];
    for (int i = tid; i < G4; i += blockDim.x)
        sB[i] = b1[i] + b2[i];
    __syncthreads();

    size_t row = (size_t)blockIdx.x * blockDim.x + tid;
    const float4* xr = reinterpret_cast<const float4*>(x) + row * 16;

    float acc[G4];
#pragma unroll
    for (int g = 0; g < G4; g++) acc[g] = sB[g];

    for (int kk = 0; kk < 16; kk++) {
        float4 xv = xr[kk];
#pragma unroll
        for (int g = 0; g < G4; g++) {
            float4 wv = sW[g * 16 + kk];
            acc[g] += xv.x * wv.x + xv.y * wv.y + xv.z * wv.z + xv.w * wv.w;
        }
    }
    float* o = d_XG + row * G4;
#pragma unroll
    for (int g = 0; g < G4; g++) o[g] = acc[g];
}

// ---------------------------------------------------------------------------
// K3: xg2[row, g] = sum_j y1[row,j]*Wih2[g,j] + (bih2[g]+bhh2[g])
// ---------------------------------------------------------------------------
__global__ __launch_bounds__(256) void k_hidgemm(
    const float* __restrict__ W,      // [40, 10]
    const float* __restrict__ b1,
    const float* __restrict__ b2)
{
    __shared__ float sW[G4 * HH];
    __shared__ float sB[G4];
    int tid = threadIdx.x;
    for (int i = tid; i < G4 * HH; i += blockDim.x) sW[i] = W[i];
    for (int i = tid; i < G4; i += blockDim.x) sB[i] = b1[i] + b2[i];
    __syncthreads();

    size_t row = (size_t)blockIdx.x * blockDim.x + tid;
    const float* yr = d_Y1 + row * HH;
    float yv[HH];
#pragma unroll
    for (int j = 0; j < HH; j++) yv[j] = yr[j];

    float* o = d_XG + row * G4;
#pragma unroll
    for (int g = 0; g < G4; g++) {
        float acc = sB[g];
#pragma unroll
        for (int j = 0; j < HH; j++) acc += yv[j] * sW[g * HH + j];
        o[g] = acc;
    }
}

// ---------------------------------------------------------------------------
// K2: layer-1 recurrence. One warp per batch. Lane k (k<10) owns hidden unit k.
// Reads d_XG, writes d_Y1 and final (h,c) into d_h1T/d_c1T.
// ---------------------------------------------------------------------------
__global__ __launch_bounds__(128) void k_lstm1(
    const float* __restrict__ Whh,    // [40, 10]
    const float* __restrict__ h0,     // [1, B, 10]
    const float* __restrict__ c0)
{
    int warp = (blockIdx.x * blockDim.x + threadIdx.x) >> 5;
    int lane = threadIdx.x & 31;
    int k = lane % HH;                // lanes >= 10 duplicate unit (lane-10 etc.), results unused

    float wi[HH], wf[HH], wg[HH], wo[HH];
#pragma unroll
    for (int j = 0; j < HH; j++) {
        wi[j] = Whh[(0 * HH + k) * HH + j];
        wf[j] = Whh[(1 * HH + k) * HH + j];
        wg[j] = Whh[(2 * HH + k) * HH + j];
        wo[j] = Whh[(3 * HH + k) * HH + j];
    }
    float h = h0[warp * HH + k];
    float c = c0[warp * HH + k];

    const float* base = d_XG + (size_t)warp * TT * G4;
    float* yb = d_Y1 + (size_t)warp * TT * HH;

    // software pipeline, prefetch distance 2
    float a0 = base[k],      a1 = base[HH + k],      a2 = base[2 * HH + k],      a3 = base[3 * HH + k];
    float p0 = base[G4 + k], p1 = base[G4 + HH + k], p2 = base[G4 + 2 * HH + k], p3 = base[G4 + 3 * HH + k];

    for (int t = 0; t < TT; t++) {
        float gi = a0, gf = a1, gg = a2, go = a3;
        a0 = p0; a1 = p1; a2 = p2; a3 = p3;
        if (t + 2 < TT) {
            const float* p = base + (size_t)(t + 2) * G4;
            p0 = p[k]; p1 = p[HH + k]; p2 = p[2 * HH + k]; p3 = p[3 * HH + k];
        }

        float hv[HH];
#pragma unroll
        for (int j = 0; j < HH; j++) hv[j] = __shfl_sync(0xffffffffu, h, j);
#pragma unroll
        for (int j = 0; j < HH; j++) {
            gi += wi[j] * hv[j];
            gf += wf[j] * hv[j];
            gg += wg[j] * hv[j];
            go += wo[j] * hv[j];
        }
        float si = fsigmoid(gi);
        float sf = fsigmoid(gf);
        float so = fsigmoid(go);
        float tg = ftanh_(gg);
        c = sf * c + si * tg;
        float tc = ftanh_(c);
        h = so * tc;

        if (lane < HH) yb[(size_t)t * HH + k] = h;
    }
    if (lane < HH) {
        d_h1T[warp * HH + k] = h;
        d_c1T[warp * HH + k] = c;
    }
}

// ---------------------------------------------------------------------------
// K4: layer-2 recurrence + fused FC output.
// out[b] = sum_t fc2w[t]*(h2[b,t] . fc1w) + fc1b * sum_t fc2w[t] + fc2b
// ---------------------------------------------------------------------------
__global__ __launch_bounds__(128) void k_lstm2(
    const float* __restrict__ Whh,    // [40, 10]
    const float* __restrict__ fc1w,   // [1, 10]
    const float* __restrict__ fc1b,   // [1]
    const float* __restrict__ fc2w,   // [1, 1024]
    const float* __restrict__ fc2b,   // [1]
    float* __restrict__ out)          // [B]
{
    int warp = (blockIdx.x * blockDim.x + threadIdx.x) >> 5;
    int lane = threadIdx.x & 31;
    int k = lane % HH;

    float wi[HH], wf[HH], wg[HH], wo[HH];
#pragma unroll
    for (int j = 0; j < HH; j++) {
        wi[j] = Whh[(0 * HH + k) * HH + j];
        wf[j] = Whh[(1 * HH + k) * HH + j];
        wg[j] = Whh[(2 * HH + k) * HH + j];
        wo[j] = Whh[(3 * HH + k) * HH + j];
    }
    float h = d_h1T[warp * HH + k];
    float c = d_c1T[warp * HH + k];

    const float* base = d_XG + (size_t)warp * TT * G4;

    float a0 = base[k],      a1 = base[HH + k],      a2 = base[2 * HH + k],      a3 = base[3 * HH + k];
    float p0 = base[G4 + k], p1 = base[G4 + HH + k], p2 = base[G4 + 2 * HH + k], p3 = base[G4 + 3 * HH + k];

    float acc = 0.0f;      // sum_t h_k * fc2w[t]
    float s2  = 0.0f;      // sum_t fc2w[t]

    for (int t = 0; t < TT; t++) {
        float gi = a0, gf = a1, gg = a2, go = a3;
        a0 = p0; a1 = p1; a2 = p2; a3 = p3;
        if (t + 2 < TT) {
            const float* p = base + (size_t)(t + 2) * G4;
            p0 = p[k]; p1 = p[HH + k]; p2 = p[2 * HH + k]; p3 = p[3 * HH + k];
        }

        float hv[HH];
#pragma unroll
        for (int j = 0; j < HH; j++) hv[j] = __shfl_sync(0xffffffffu, h, j);
#pragma unroll
        for (int j = 0; j < HH; j++) {
            gi += wi[j] * hv[j];
            gf += wf[j] * hv[j];
            gg += wg[j] * hv[j];
            go += wo[j] * hv[j];
        }
        float si = fsigmoid(gi);
        float sf = fsigmoid(gf);
        float so = fsigmoid(go);
        float tg = ftanh_(gg);
        c = sf * c + si * tg;
        float tc = ftanh_(c);
        h = so * tc;

        float fw = __ldg(fc2w + t);
        acc += h * fw;
        s2  += fw;
    }

    float val = (lane < HH) ? acc * fc1w[k] : 0.0f;
#pragma unroll
    for (int off = 16; off > 0; off >>= 1)
        val += __shfl_xor_sync(0xffffffffu, val, off);
    if (lane == 0)
        out[warp] = val + fc1b[0] * s2 + fc2b[0];
}

// ---------------------------------------------------------------------------
extern "C" void kernel_launch(void* const* d_in, const int* in_sizes, int n_in,
                              void* d_out, int out_size)
{
    const float* x     = (const float*)d_in[0];
    const float* h0    = (const float*)d_in[1];
    const float* c0    = (const float*)d_in[2];
    const float* Wih1  = (const float*)d_in[3];
    const float* Whh1  = (const float*)d_in[4];
    const float* bih1  = (const float*)d_in[5];
    const float* bhh1  = (const float*)d_in[6];
    const float* Wih2  = (const float*)d_in[7];
    const float* Whh2  = (const float*)d_in[8];
    const float* bih2  = (const float*)d_in[9];
    const float* bhh2  = (const float*)d_in[10];
    const float* fc1w  = (const float*)d_in[11];
    const float* fc1b  = (const float*)d_in[12];
    const float* fc2w  = (const float*)d_in[13];
    const float* fc2b  = (const float*)d_in[14];
    float* out = (float*)d_out;

    // B*T = 524288 rows; 2048 blocks x 256 threads covers exactly
    k_inputgemm<<<2048, 256>>>(x, Wih1, bih1, bhh1);
    k_lstm1<<<128, 128>>>(Whh1, h0, c0);           // 512 warps = 512 batches
    k_hidgemm<<<2048, 256>>>(Wih2, bih2, bhh2);
    k_lstm2<<<128, 128>>>(Whh2, fc1w, fc1b, fc2w, fc2b, out);
}

// round 2
// speedup vs baseline: 2.2659x; 2.2659x over previous
#include <cuda_runtime.h>

#define BB 512
#define TT 1024
#define IDIM 64
#define HH 10
#define G4 40   // 4*H

// Scratch (static device globals — no runtime allocation)
__device__ float d_XG[BB * TT * G4];   // gate pre-activations, PERMUTED layout (see below)
__device__ float d_Y1[BB * TT * HH];   // layer-1 hidden outputs
__device__ float d_h1T[BB * HH];
__device__ float d_c1T[BB * HH];

// Permuted per-row gate layout (40 floats):
//   pos 0..19 : (i_u, g_u) pairs for u=0..9   -> float2 index u
//   pos 20..39: (f_u, o_u) pairs for u=0..9   -> float2 index 10+u
// old gate row for new position p:
__device__ __forceinline__ int old_gate(int p) {
    if (p < 20) { int u = p >> 1; return (p & 1) ? 20 + u : u; }       // g : i
    int q = p - 20; int u = q >> 1; return (q & 1) ? 30 + u : 10 + u;  // o : f
}

__device__ __forceinline__ float tanh_ap(float x) {
    float y;
    asm("tanh.approx.f32 %0, %1;" : "=f"(y) : "f"(x));
    return y;
}
__device__ __forceinline__ float sig_ap(float x) {
    return fmaf(tanh_ap(0.5f * x), 0.5f, 0.5f);
}

// ---------------------------------------------------------------------------
// K1: input GEMM. Thread = 4 rows x 10 (permuted) gates. Weights in smem
// (already permuted at fill time), x via LDG.128, 2560 FFMA / thread.
// ---------------------------------------------------------------------------
__global__ __launch_bounds__(256) void k_inputgemm(
    const float* __restrict__ x,      // [B*T, 64]
    const float* __restrict__ W,      // [40, 64]
    const float* __restrict__ b1,
    const float* __restrict__ b2)
{
    __shared__ float4 sW[G4 * 16];    // permuted rows
    __shared__ float  sB[G4];
    int tid = threadIdx.x;
    for (int p = tid; p < G4 * 16; p += 256) {
        int row = p >> 4, kk = p & 15;
        sW[p] = reinterpret_cast<const float4*>(W)[old_gate(row) * 16 + kk];
    }
    for (int p = tid; p < G4; p += 256) {
        int o = old_gate(p);
        sB[p] = b1[o] + b2[o];
    }
    __syncthreads();

    int gt = blockIdx.x * 256 + tid;
    int rowblk = gt >> 2;             // 131072 row-blocks of 4 rows
    int q = gt & 3;                   // gate group: new gates [q*10, q*10+10)
    size_t r0 = (size_t)rowblk * 4;

    float acc[4][10];
#pragma unroll
    for (int r = 0; r < 4; r++)
#pragma unroll
        for (int g = 0; g < 10; g++) acc[r][g] = sB[q * 10 + g];

    const float4* x4 = reinterpret_cast<const float4*>(x);
    for (int kk = 0; kk < 16; kk++) {
        float4 xv[4];
#pragma unroll
        for (int r = 0; r < 4; r++) xv[r] = x4[(r0 + r) * 16 + kk];
#pragma unroll
        for (int g = 0; g < 10; g++) {
            float4 wv = sW[(q * 10 + g) * 16 + kk];
#pragma unroll
            for (int r = 0; r < 4; r++) {
                acc[r][g] = fmaf(xv[r].x, wv.x, acc[r][g]);
                acc[r][g] = fmaf(xv[r].y, wv.y, acc[r][g]);
                acc[r][g] = fmaf(xv[r].z, wv.z, acc[r][g]);
                acc[r][g] = fmaf(xv[r].w, wv.w, acc[r][g]);
            }
        }
    }
#pragma unroll
    for (int r = 0; r < 4; r++) {
        float2* o2 = reinterpret_cast<float2*>(d_XG + (r0 + r) * G4 + q * 10);
#pragma unroll
        for (int g = 0; g < 5; g++)
            o2[g] = make_float2(acc[r][2 * g], acc[r][2 * g + 1]);
    }
}

// ---------------------------------------------------------------------------
// K3: hidden GEMM (y1 @ Wih2^T + b), same permuted output layout.
// Thread = 2 rows x 10 gates.
// ---------------------------------------------------------------------------
__global__ __launch_bounds__(256) void k_hidgemm(
    const float* __restrict__ W,      // [40, 10]
    const float* __restrict__ b1,
    const float* __restrict__ b2)
{
    __shared__ float sW[G4 * HH];     // permuted rows
    __shared__ float sB[G4];
    int tid = threadIdx.x;
    for (int p = tid; p < G4 * HH; p += 256) {
        int row = p / HH, j = p % HH;
        sW[p] = W[old_gate(row) * HH + j];
    }
    for (int p = tid; p < G4; p += 256) {
        int o = old_gate(p);
        sB[p] = b1[o] + b2[o];
    }
    __syncthreads();

    int gt = blockIdx.x * 256 + tid;
    int rowblk = gt >> 2;             // 262144 row-blocks of 2 rows
    int q = gt & 3;
    size_t r0 = (size_t)rowblk * 2;

    float yv[2][10];
#pragma unroll
    for (int r = 0; r < 2; r++) {
        const float2* y2 = reinterpret_cast<const float2*>(d_Y1 + (r0 + r) * HH);
#pragma unroll
        for (int j = 0; j < 5; j++) {
            float2 v = y2[j];
            yv[r][2 * j] = v.x;
            yv[r][2 * j + 1] = v.y;
        }
    }

    float acc[2][10];
#pragma unroll
    for (int r = 0; r < 2; r++)
#pragma unroll
        for (int g = 0; g < 10; g++) acc[r][g] = sB[q * 10 + g];

#pragma unroll
    for (int g = 0; g < 10; g++) {
        const float* w = &sW[(q * 10 + g) * HH];
#pragma unroll
        for (int j = 0; j < 10; j++) {
            float wj = w[j];
            acc[0][g] = fmaf(yv[0][j], wj, acc[0][g]);
            acc[1][g] = fmaf(yv[1][j], wj, acc[1][g]);
        }
    }
#pragma unroll
    for (int r = 0; r < 2; r++) {
        float2* o2 = reinterpret_cast<float2*>(d_XG + (r0 + r) * G4 + q * 10);
#pragma unroll
        for (int g = 0; g < 5; g++)
            o2[g] = make_float2(acc[r][2 * g], acc[r][2 * g + 1]);
    }
}

// ---------------------------------------------------------------------------
// Recurrence step, gate-split across lanes.
//   role 0 (lanes 0-9, 20-29):  unit k computes gates (i, g)
//   role 1 (lanes 10-19, 30-31): unit k computes gates (f, o)
// Lane k<10 owns (h_k, c_k); gathers sf/so from lane 10+k.
// ---------------------------------------------------------------------------
#define LSTM_STEP(ab, fw_opt)                                                 \
    {                                                                         \
        float eA = fmaf(wA[0], hv[0], (ab).x);                                \
        eA = fmaf(wA[2], hv[2], eA); eA = fmaf(wA[4], hv[4], eA);             \
        eA = fmaf(wA[6], hv[6], eA); eA = fmaf(wA[8], hv[8], eA);             \
        float oA = wA[1] * hv[1];                                             \
        oA = fmaf(wA[3], hv[3], oA); oA = fmaf(wA[5], hv[5], oA);             \
        oA = fmaf(wA[7], hv[7], oA); oA = fmaf(wA[9], hv[9], oA);             \
        float gA = eA + oA;                                                   \
        float eB = fmaf(wB[0], hv[0], (ab).y);                                \
        eB = fmaf(wB[2], hv[2], eB); eB = fmaf(wB[4], hv[4], eB);             \
        eB = fmaf(wB[6], hv[6], eB); eB = fmaf(wB[8], hv[8], eB);             \
        float oB = wB[1] * hv[1];                                             \
        oB = fmaf(wB[3], hv[3], oB); oB = fmaf(wB[5], hv[5], oB);             \
        oB = fmaf(wB[7], hv[7], oB); oB = fmaf(wB[9], hv[9], oB);             \
        float gB = eB + oB;                                                   \
        float actA = sig_ap(gA);                  /* sigmoid(i) or sigmoid(f) */ \
        float actB = fmaf(tanh_ap(mB * gB), aB, bB); /* tanh(g) or sigmoid(o) */ \
        float sf = __shfl_sync(0xffffffffu, actA, 10 + k);                    \
        float so = __shfl_sync(0xffffffffu, actB, 10 + k);                    \
        float prod = actA * actB;                 /* si*tg on role0 lanes */  \
        c = fmaf(sf, c, prod);                                                \
        float tc = tanh_ap(c);                                                \
        h = so * tc;                                                          \
        _Pragma("unroll")                                                     \
        for (int j = 0; j < 10; j++) hv[j] = __shfl_sync(0xffffffffu, h, j);  \
        fw_opt                                                                \
    }

__global__ __launch_bounds__(128) void k_lstm1(
    const float* __restrict__ Whh,    // [40, 10] (unpermuted)
    const float* __restrict__ h0,
    const float* __restrict__ c0)
{
    int warp = (blockIdx.x * blockDim.x + threadIdx.x) >> 5;
    int lane = threadIdx.x & 31;
    int k = lane % HH;
    int role = (lane / HH) & 1;

    int rA = role ? 10 + k : k;       // f : i
    int rB = role ? 30 + k : 20 + k;  // o : g
    float wA[10], wB[10];
#pragma unroll
    for (int j = 0; j < 10; j++) {
        wA[j] = Whh[rA * HH + j];
        wB[j] = Whh[rB * HH + j];
    }
    float mB = role ? 0.5f : 1.0f;
    float aB = role ? 0.5f : 1.0f;
    float bB = role ? 0.5f : 0.0f;

    float h = h0[warp * HH + k];
    float c = c0[warp * HH + k];
    float hv[10];
#pragma unroll
    for (int j = 0; j < 10; j++) hv[j] = __shfl_sync(0xffffffffu, h, j);

    const float2* base =
        reinterpret_cast<const float2*>(d_XG + (size_t)warp * TT * G4) + role * 10 + k;
    float* yb = d_Y1 + (size_t)warp * TT * HH;

    float2 cur[4], nxt[4];
#pragma unroll
    for (int i = 0; i < 4; i++) cur[i] = base[i * 20];
#pragma unroll
    for (int i = 0; i < 4; i++) nxt[i] = base[(4 + i) * 20];

    for (int t = 0; t < TT; t += 4) {
        float2 pf[4];
        if (t + 8 < TT) {
#pragma unroll
            for (int i = 0; i < 4; i++) pf[i] = base[(t + 8 + i) * 20];
        }
#pragma unroll
        for (int s = 0; s < 4; s++) {
            LSTM_STEP(cur[s], {
                if (lane < HH) yb[(size_t)(t + s) * HH + k] = h;
            });
        }
#pragma unroll
        for (int i = 0; i < 4; i++) { cur[i] = nxt[i]; nxt[i] = pf[i]; }
    }
    if (lane < HH) {
        d_h1T[warp * HH + k] = h;
        d_c1T[warp * HH + k] = c;
    }
}

__global__ __launch_bounds__(128) void k_lstm2(
    const float* __restrict__ Whh,    // [40, 10]
    const float* __restrict__ fc1w,   // [1, 10]
    const float* __restrict__ fc1b,
    const float* __restrict__ fc2w,   // [1, 1024]
    const float* __restrict__ fc2b,
    float* __restrict__ out)          // [B]
{
    int warp = (blockIdx.x * blockDim.x + threadIdx.x) >> 5;
    int lane = threadIdx.x & 31;
    int k = lane % HH;
    int role = (lane / HH) & 1;

    int rA = role ? 10 + k : k;
    int rB = role ? 30 + k : 20 + k;
    float wA[10], wB[10];
#pragma unroll
    for (int j = 0; j < 10; j++) {
        wA[j] = Whh[rA * HH + j];
        wB[j] = Whh[rB * HH + j];
    }
    float mB = role ? 0.5f : 1.0f;
    float aB = role ? 0.5f : 1.0f;
    float bB = role ? 0.5f : 0.0f;

    float h = d_h1T[warp * HH + k];
    float c = d_c1T[warp * HH + k];
    float hv[10];
#pragma unroll
    for (int j = 0; j < 10; j++) hv[j] = __shfl_sync(0xffffffffu, h, j);

    const float2* base =
        reinterpret_cast<const float2*>(d_XG + (size_t)warp * TT * G4) + role * 10 + k;
    const float4* f4 = reinterpret_cast<const float4*>(fc2w);

    float2 cur[4], nxt[4];
#pragma unroll
    for (int i = 0; i < 4; i++) cur[i] = base[i * 20];
#pragma unroll
    for (int i = 0; i < 4; i++) nxt[i] = base[(4 + i) * 20];

    float acc = 0.0f;   // sum_t h_k * fc2w[t]
    float s2 = 0.0f;    // sum_t fc2w[t]

    for (int t = 0; t < TT; t += 4) {
        float2 pf[4];
        if (t + 8 < TT) {
#pragma unroll
            for (int i = 0; i < 4; i++) pf[i] = base[(t + 8 + i) * 20];
        }
        float4 fwv = __ldg(&f4[t >> 2]);
        float fw4[4] = {fwv.x, fwv.y, fwv.z, fwv.w};
#pragma unroll
        for (int s = 0; s < 4; s++) {
            LSTM_STEP(cur[s], {
                acc = fmaf(h, fw4[s], acc);
                s2 += fw4[s];
            });
        }
#pragma unroll
        for (int i = 0; i < 4; i++) { cur[i] = nxt[i]; nxt[i] = pf[i]; }
    }

    float val = (lane < HH) ? acc * fc1w[k] : 0.0f;
#pragma unroll
    for (int off = 16; off > 0; off >>= 1)
        val += __shfl_xor_sync(0xffffffffu, val, off);
    if (lane == 0)
        out[warp] = val + fc1b[0] * s2 + fc2b[0];
}

// ---------------------------------------------------------------------------
extern "C" void kernel_launch(void* const* d_in, const int* in_sizes, int n_in,
                              void* d_out, int out_size)
{
    const float* x    = (const float*)d_in[0];
    const float* h0   = (const float*)d_in[1];
    const float* c0   = (const float*)d_in[2];
    const float* Wih1 = (const float*)d_in[3];
    const float* Whh1 = (const float*)d_in[4];
    const float* bih1 = (const float*)d_in[5];
    const float* bhh1 = (const float*)d_in[6];
    const float* Wih2 = (const float*)d_in[7];
    const float* Whh2 = (const float*)d_in[8];
    const float* bih2 = (const float*)d_in[9];
    const float* bhh2 = (const float*)d_in[10];
    const float* fc1w = (const float*)d_in[11];
    const float* fc1b = (const float*)d_in[12];
    const float* fc2w = (const float*)d_in[13];
    const float* fc2b = (const float*)d_in[14];
    float* out = (float*)d_out;

    k_inputgemm<<<2048, 256>>>(x, Wih1, bih1, bhh1);       // 524288 threads
    k_lstm1<<<128, 128>>>(Whh1, h0, c0);                   // 512 warps
    k_hidgemm<<<4096, 256>>>(Wih2, bih2, bhh2);            // 1048576 threads
    k_lstm2<<<128, 128>>>(Whh2, fc1w, fc1b, fc2w, fc2b, out);
}

// round 4
// speedup vs baseline: 2.5302x; 1.1166x over previous
#include <cuda_runtime.h>

#define BB 512
#define TT 1024
#define IDIM 64
#define HH 10
#define G4 40   // 4*H

typedef unsigned long long u64;

// Scratch (static device globals — no runtime allocation)
__device__ float d_XG1[BB * TT * G4];  // layer-1 gate preacts, unit-interleaved (i,f,g,o) per unit
__device__ float d_XG2[BB * TT * G4];  // layer-2 gate preacts, same layout (written by fused lstm1)
__device__ float d_h1T[BB * HH];
__device__ float d_c1T[BB * HH];

// New layout: position p = 4*u + gt  (u = unit, gt in {i,f,g,o}).
// Original PyTorch gate-row for position p:
__device__ __forceinline__ int old_gate(int p) {
    int u = p >> 2, gt = p & 3;
    return gt * HH + u;
}

__device__ __forceinline__ float tanh_ap(float x) {
    float y;
    asm("tanh.approx.f32 %0, %1;" : "=f"(y) : "f"(x));
    return y;
}

// ---- packed f32x2 helpers (sm_100+) ----
__device__ __forceinline__ u64 pk2(float lo, float hi) {
    u64 r; asm("mov.b64 %0, {%1, %2};" : "=l"(r) : "f"(lo), "f"(hi)); return r;
}
__device__ __forceinline__ void upk2(float& lo, float& hi, u64 v) {
    asm("mov.b64 {%0, %1}, %2;" : "=f"(lo), "=f"(hi) : "l"(v));
}
__device__ __forceinline__ u64 fma2(u64 a, u64 b, u64 c) {
    u64 d; asm("fma.rn.f32x2 %0, %1, %2, %3;" : "=l"(d) : "l"(a), "l"(b), "l"(c)); return d;
}
__device__ __forceinline__ u64 mul2(u64 a, u64 b) {
    u64 d; asm("mul.rn.f32x2 %0, %1, %2;" : "=l"(d) : "l"(a), "l"(b)); return d;
}
__device__ __forceinline__ u64 add2(u64 a, u64 b) {
    u64 d; asm("add.rn.f32x2 %0, %1, %2;" : "=l"(d) : "l"(a), "l"(b)); return d;
}

// ---------------------------------------------------------------------------
// K1: input GEMM -> d_XG1 (unit-interleaved layout). Thread = 4 rows x 10
// consecutive layout positions (q*10..q*10+9).
// ---------------------------------------------------------------------------
__global__ __launch_bounds__(256) void k_inputgemm(
    const float* __restrict__ x,      // [B*T, 64]
    const float* __restrict__ W,      // [40, 64] (orig gate order)
    const float* __restrict__ b1,
    const float* __restrict__ b2)
{
    __shared__ float4 sW[G4 * 16];    // permuted rows (new-layout order)
    __shared__ float  sB[G4];
    int tid = threadIdx.x;
    for (int p = tid; p < G4 * 16; p += 256) {
        int row = p >> 4, kk = p & 15;
        sW[p] = reinterpret_cast<const float4*>(W)[old_gate(row) * 16 + kk];
    }
    for (int p = tid; p < G4; p += 256) {
        int o = old_gate(p);
        sB[p] = b1[o] + b2[o];
    }
    __syncthreads();

    int gt = blockIdx.x * 256 + tid;
    int rowblk = gt >> 2;
    int q = gt & 3;
    size_t r0 = (size_t)rowblk * 4;

    float acc[4][10];
#pragma unroll
    for (int r = 0; r < 4; r++)
#pragma unroll
        for (int g = 0; g < 10; g++) acc[r][g] = sB[q * 10 + g];

    const float4* x4 = reinterpret_cast<const float4*>(x);
    for (int kk = 0; kk < 16; kk++) {
        float4 xv[4];
#pragma unroll
        for (int r = 0; r < 4; r++) xv[r] = x4[(r0 + r) * 16 + kk];
#pragma unroll
        for (int g = 0; g < 10; g++) {
            float4 wv = sW[(q * 10 + g) * 16 + kk];
#pragma unroll
            for (int r = 0; r < 4; r++) {
                acc[r][g] = fmaf(xv[r].x, wv.x, acc[r][g]);
                acc[r][g] = fmaf(xv[r].y, wv.y, acc[r][g]);
                acc[r][g] = fmaf(xv[r].z, wv.z, acc[r][g]);
                acc[r][g] = fmaf(xv[r].w, wv.w, acc[r][g]);
            }
        }
    }
#pragma unroll
    for (int r = 0; r < 4; r++) {
        float2* o2 = reinterpret_cast<float2*>(d_XG1 + (r0 + r) * G4 + q * 10);
#pragma unroll
        for (int g = 0; g < 5; g++)
            o2[g] = make_float2(acc[r][2 * g], acc[r][2 * g + 1]);
    }
}

// ---------------------------------------------------------------------------
// Recurrence core. One warp per batch. Lane k (k = lane%10) owns unit k and
// computes ALL 4 of its gates via packed f32x2 ((i,f) and (g,o) pairs).
// Only one shfl stage (h broadcast) is on the critical path.
// ---------------------------------------------------------------------------
#define LSTM_STEP_CORE(abx, aby)                                              \
    {                                                                         \
        u64 eIF = fma2(wIF[0], hvp[0], (abx));                                \
        eIF = fma2(wIF[2], hvp[2], eIF);                                      \
        eIF = fma2(wIF[4], hvp[4], eIF);                                      \
        eIF = fma2(wIF[6], hvp[6], eIF);                                      \
        eIF = fma2(wIF[8], hvp[8], eIF);                                      \
        u64 oIF = mul2(wIF[1], hvp[1]);                                       \
        oIF = fma2(wIF[3], hvp[3], oIF);                                      \
        oIF = fma2(wIF[5], hvp[5], oIF);                                      \
        oIF = fma2(wIF[7], hvp[7], oIF);                                      \
        oIF = fma2(wIF[9], hvp[9], oIF);                                      \
        u64 gIF = add2(eIF, oIF);                                             \
        u64 eGO = fma2(wGO[0], hvp[0], (aby));                                \
        eGO = fma2(wGO[2], hvp[2], eGO);                                      \
        eGO = fma2(wGO[4], hvp[4], eGO);                                      \
        eGO = fma2(wGO[6], hvp[6], eGO);                                      \
        eGO = fma2(wGO[8], hvp[8], eGO);                                      \
        u64 oGO = mul2(wGO[1], hvp[1]);                                       \
        oGO = fma2(wGO[3], hvp[3], oGO);                                      \
        oGO = fma2(wGO[5], hvp[5], oGO);                                      \
        oGO = fma2(wGO[7], hvp[7], oGO);                                      \
        oGO = fma2(wGO[9], hvp[9], oGO);                                      \
        u64 gGO = add2(eGO, oGO);                                             \
        u64 sIF = mul2(gIF, cHH);   /* (gi/2, gf/2) */                        \
        u64 sGO = mul2(gGO, cOH);   /* (gg, go/2)  */                         \
        float xi, xf, xg, xo;                                                 \
        upk2(xi, xf, sIF);                                                    \
        upk2(xg, xo, sGO);                                                    \
        float ti = tanh_ap(xi);                                               \
        float tg = tanh_ap(xg);                                               \
        float tf = tanh_ap(xf);                                               \
        float to_ = tanh_ap(xo);                                              \
        float si = fmaf(ti, 0.5f, 0.5f);                                      \
        float sf = fmaf(tf, 0.5f, 0.5f);                                      \
        float so = fmaf(to_, 0.5f, 0.5f);                                     \
        c = fmaf(sf, c, si * tg);                                             \
        float tc = tanh_ap(c);                                                \
        h = so * tc;                                                          \
        _Pragma("unroll")                                                     \
        for (int j = 0; j < 10; j++) {                                        \
            float hj = __shfl_sync(0xffffffffu, h, j);                        \
            hvp[j] = pk2(hj, hj);                                             \
        }                                                                     \
    }

// lstm1: reads d_XG1, runs layer-1 recurrence, and fuses the layer-2 input
// GEMM: xg2[t] = Wih2 * h1[t] + (bih2+bhh2), written to d_XG2 (packed pairs,
// lanes 0..19 each own output positions (2l, 2l+1)).
__global__ __launch_bounds__(128) void k_lstm1(
    const float* __restrict__ Whh,    // [40,10] layer-1 (orig order)
    const float* __restrict__ h0,
    const float* __restrict__ c0,
    const float* __restrict__ Wih2,   // [40,10]
    const float* __restrict__ bih2,
    const float* __restrict__ bhh2)
{
    int warp = (blockIdx.x * blockDim.x + threadIdx.x) >> 5;
    int lane = threadIdx.x & 31;
    int k = lane % HH;

    // recurrent weights, packed (i,f) and (g,o)
    u64 wIF[10], wGO[10];
#pragma unroll
    for (int j = 0; j < 10; j++) {
        wIF[j] = pk2(Whh[(0 * HH + k) * HH + j], Whh[(1 * HH + k) * HH + j]);
        wGO[j] = pk2(Whh[(2 * HH + k) * HH + j], Whh[(3 * HH + k) * HH + j]);
    }
    // fused-gemm weights: lane l owns output positions (2l, 2l+1) of the
    // interleaved layout. 2l = 4u+gg: u = l>>1; even l -> (i,f), odd -> (g,o).
    int l2 = (lane < 20) ? lane : lane - 20;
    int u2 = l2 >> 1;
    int rA = (l2 & 1) ? (2 * HH + u2) : u2;   // i or g row
    int rB = rA + HH;                          // f or o row
    u64 w2p[10];
#pragma unroll
    for (int j = 0; j < 10; j++)
        w2p[j] = pk2(Wih2[rA * HH + j], Wih2[rB * HH + j]);
    u64 b2p = pk2(bih2[rA] + bhh2[rA], bih2[rB] + bhh2[rB]);

    u64 cHH = pk2(0.5f, 0.5f);
    u64 cOH = pk2(1.0f, 0.5f);

    float h = h0[warp * HH + k];
    float c = c0[warp * HH + k];
    u64 hvp[10];
#pragma unroll
    for (int j = 0; j < 10; j++) {
        float hj = __shfl_sync(0xffffffffu, h, j);
        hvp[j] = pk2(hj, hj);
    }

    const ulonglong2* base =
        reinterpret_cast<const ulonglong2*>(d_XG1) + (size_t)warp * TT * HH + k;
    u64* out2 = reinterpret_cast<u64*>(d_XG2) + (size_t)warp * TT * (G4 / 2) + lane;

    ulonglong2 cur[4], nxt[4];
#pragma unroll
    for (int i = 0; i < 4; i++) cur[i] = base[i * HH];
#pragma unroll
    for (int i = 0; i < 4; i++) nxt[i] = base[(4 + i) * HH];

    for (int t = 0; t < TT; t += 4) {
        ulonglong2 pf[4];
        if (t + 8 < TT) {
#pragma unroll
            for (int i = 0; i < 4; i++) pf[i] = base[(size_t)(t + 8 + i) * HH];
        }
#pragma unroll
        for (int s = 0; s < 4; s++) {
            LSTM_STEP_CORE(cur[s].x, cur[s].y);
            // fused layer-2 input gemm for step t+s (uses NEW hvp = h1[t+s])
            u64 acc = fma2(w2p[0], hvp[0], b2p);
            acc = fma2(w2p[1], hvp[1], acc);
            acc = fma2(w2p[2], hvp[2], acc);
            acc = fma2(w2p[3], hvp[3], acc);
            acc = fma2(w2p[4], hvp[4], acc);
            acc = fma2(w2p[5], hvp[5], acc);
            acc = fma2(w2p[6], hvp[6], acc);
            acc = fma2(w2p[7], hvp[7], acc);
            acc = fma2(w2p[8], hvp[8], acc);
            acc = fma2(w2p[9], hvp[9], acc);
            if (lane < 20) out2[(size_t)(t + s) * (G4 / 2)] = acc;
        }
#pragma unroll
        for (int i = 0; i < 4; i++) { cur[i] = nxt[i]; nxt[i] = pf[i]; }
    }
    if (lane < HH) {
        d_h1T[warp * HH + k] = h;
        d_c1T[warp * HH + k] = c;
    }
}

// lstm2: reads d_XG2, runs layer-2 recurrence, fuses the FC chain:
// out[b] = sum_t fc2w[t]*(h2[b,t].fc1w) + fc1b*sum_t fc2w[t] + fc2b
__global__ __launch_bounds__(128) void k_lstm2(
    const float* __restrict__ Whh,    // [40,10] layer-2
    const float* __restrict__ fc1w,
    const float* __restrict__ fc1b,
    const float* __restrict__ fc2w,   // [1024]
    const float* __restrict__ fc2b,
    float* __restrict__ out)
{
    int warp = (blockIdx.x * blockDim.x + threadIdx.x) >> 5;
    int lane = threadIdx.x & 31;
    int k = lane % HH;

    u64 wIF[10], wGO[10];
#pragma unroll
    for (int j = 0; j < 10; j++) {
        wIF[j] = pk2(Whh[(0 * HH + k) * HH + j], Whh[(1 * HH + k) * HH + j]);
        wGO[j] = pk2(Whh[(2 * HH + k) * HH + j], Whh[(3 * HH + k) * HH + j]);
    }
    u64 cHH = pk2(0.5f, 0.5f);
    u64 cOH = pk2(1.0f, 0.5f);

    float h = d_h1T[warp * HH + k];
    float c = d_c1T[warp * HH + k];
    u64 hvp[10];
#pragma unroll
    for (int j = 0; j < 10; j++) {
        float hj = __shfl_sync(0xffffffffu, h, j);
        hvp[j] = pk2(hj, hj);
    }

    const ulonglong2* base =
        reinterpret_cast<const ulonglong2*>(d_XG2) + (size_t)warp * TT * HH + k;
    const float4* f4 = reinterpret_cast<const float4*>(fc2w);

    ulonglong2 cur[4], nxt[4];
#pragma unroll
    for (int i = 0; i < 4; i++) cur[i] = base[i * HH];
#pragma unroll
    for (int i = 0; i < 4; i++) nxt[i] = base[(4 + i) * HH];

    float acc = 0.0f;   // sum_t h_k * fc2w[t]
    float s2 = 0.0f;    // sum_t fc2w[t]

    for (int t = 0; t < TT; t += 4) {
        ulonglong2 pf[4];
        if (t + 8 < TT) {
#pragma unroll
            for (int i = 0; i < 4; i++) pf[i] = base[(size_t)(t + 8 + i) * HH];
        }
        float4 fwv = __ldg(&f4[t >> 2]);
        float fw4[4] = {fwv.x, fwv.y, fwv.z, fwv.w};
#pragma unroll
        for (int s = 0; s < 4; s++) {
            LSTM_STEP_CORE(cur[s].x, cur[s].y);
            acc = fmaf(h, fw4[s], acc);
            s2 += fw4[s];
        }
#pragma unroll
        for (int i = 0; i < 4; i++) { cur[i] = nxt[i]; nxt[i] = pf[i]; }
    }

    float val = (lane < HH) ? acc * fc1w[k] : 0.0f;
#pragma unroll
    for (int off = 16; off > 0; off >>= 1)
        val += __shfl_xor_sync(0xffffffffu, val, off);
    if (lane == 0)
        out[warp] = val + fc1b[0] * s2 + fc2b[0];
}

// ---------------------------------------------------------------------------
extern "C" void kernel_launch(void* const* d_in, const int* in_sizes, int n_in,
                              void* d_out, int out_size)
{
    const float* x    = (const float*)d_in[0];
    const float* h0   = (const float*)d_in[1];
    const float* c0   = (const float*)d_in[2];
    const float* Wih1 = (const float*)d_in[3];
    const float* Whh1 = (const float*)d_in[4];
    const float* bih1 = (const float*)d_in[5];
    const float* bhh1 = (const float*)d_in[6];
    const float* Wih2 = (const float*)d_in[7];
    const float* Whh2 = (const float*)d_in[8];
    const float* bih2 = (const float*)d_in[9];
    const float* bhh2 = (const float*)d_in[10];
    const float* fc1w = (const float*)d_in[11];
    const float* fc1b = (const float*)d_in[12];
    const float* fc2w = (const float*)d_in[13];
    const float* fc2b = (const float*)d_in[14];
    float* out = (float*)d_out;

    k_inputgemm<<<2048, 256>>>(x, Wih1, bih1, bhh1);
    k_lstm1<<<128, 128>>>(Whh1, h0, c0, Wih2, bih2, bhh2);   // fuses xg2 gemm
    k_lstm2<<<128, 128>>>(Whh2, fc1w, fc1b, fc2w, fc2b, out);
}

// round 5
// speedup vs baseline: 2.7431x; 1.0841x over previous
#include <cuda_runtime.h>

#define BB 512
#define TT 1024
#define IDIM 64
#define HH 10
#define G4 40   // 4*H

typedef unsigned long long u64;

// Scratch (static device globals — no runtime allocation)
__device__ float d_XG1[BB * TT * G4];  // layer-1 gate preacts, unit-interleaved (i,f,g,o) per unit
__device__ float d_XG2[BB * TT * G4];  // layer-2 gate preacts, same layout (written by fused lstm1)
__device__ float d_h1T[BB * HH];
__device__ float d_c1T[BB * HH];

// Layout position p = 4*u + gt (u=unit, gt in {i,f,g,o}); original gate row:
__device__ __forceinline__ int old_gate(int p) {
    int u = p >> 2, gt = p & 3;
    return gt * HH + u;
}

__device__ __forceinline__ float tanh_ap(float x) {
    float y;
    asm("tanh.approx.f32 %0, %1;" : "=f"(y) : "f"(x));
    return y;
}

// ---- packed f32x2 helpers (sm_100+) ----
__device__ __forceinline__ u64 pk2(float lo, float hi) {
    u64 r; asm("mov.b64 %0, {%1, %2};" : "=l"(r) : "f"(lo), "f"(hi)); return r;
}
__device__ __forceinline__ void upk2(float& lo, float& hi, u64 v) {
    asm("mov.b64 {%0, %1}, %2;" : "=f"(lo), "=f"(hi) : "l"(v));
}
__device__ __forceinline__ u64 fma2(u64 a, u64 b, u64 c) {
    u64 d; asm("fma.rn.f32x2 %0, %1, %2, %3;" : "=l"(d) : "l"(a), "l"(b), "l"(c)); return d;
}
__device__ __forceinline__ u64 mul2(u64 a, u64 b) {
    u64 d; asm("mul.rn.f32x2 %0, %1, %2;" : "=l"(d) : "l"(a), "l"(b)); return d;
}
__device__ __forceinline__ u64 add2(u64 a, u64 b) {
    u64 d; asm("add.rn.f32x2 %0, %1, %2;" : "=l"(d) : "l"(a), "l"(b)); return d;
}

// ---------------------------------------------------------------------------
// K1: input GEMM -> d_XG1. Thread = 4 rows x 5 gate-PAIRS (q selects pairs
// q*5..q*5+4 covering layout positions q*10..q*10+9). Weights held in smem as
// packed f32x2 pairs with a padded q-stride (322 u64 = 2576B, bank shift 4)
// so the 4 q-groups never collide on banks.
// ---------------------------------------------------------------------------
#define QSTRIDE 322   // 5*64 + 2 u64 per q-group (pad breaks 128B periodicity)

__global__ __launch_bounds__(256) void k_inputgemm(
    const float* __restrict__ x,      // [B*T, 64]
    const float* __restrict__ W,      // [40, 64] (orig gate order)
    const float* __restrict__ b1,
    const float* __restrict__ b2)
{
    __shared__ u64 sW2[4 * QSTRIDE];  // sW2[q*QSTRIDE + g2*64 + k] = (W[p],W[p+1]) at col k, p=q*10+2*g2
    __shared__ u64 sB2[20];           // bias pairs, index q*5+g2
    int tid = threadIdx.x;
    for (int e = tid; e < 1280; e += 256) {
        int q = e / 320, rem = e % 320;
        int g2 = rem >> 6, k = rem & 63;
        int p = q * 10 + 2 * g2;
        float lo = W[old_gate(p) * 64 + k];
        float hi = W[old_gate(p + 1) * 64 + k];
        sW2[q * QSTRIDE + g2 * 64 + k] = pk2(lo, hi);
    }
    for (int e = tid; e < 20; e += 256) {
        int q = e / 5, g2 = e % 5;
        int p = q * 10 + 2 * g2;
        int oA = old_gate(p), oB = old_gate(p + 1);
        sB2[e] = pk2(b1[oA] + b2[oA], b1[oB] + b2[oB]);
    }
    __syncthreads();

    int gt = blockIdx.x * 256 + tid;
    int rowblk = gt >> 2;
    int q = gt & 3;
    size_t r0 = (size_t)rowblk * 4;
    const u64* wq = &sW2[q * QSTRIDE];

    u64 acc2[4][5];
#pragma unroll
    for (int r = 0; r < 4; r++)
#pragma unroll
        for (int g2 = 0; g2 < 5; g2++) acc2[r][g2] = sB2[q * 5 + g2];

    const float4* x4 = reinterpret_cast<const float4*>(x);
    for (int kk = 0; kk < 16; kk++) {
        float4 xv[4];
#pragma unroll
        for (int r = 0; r < 4; r++) xv[r] = x4[(r0 + r) * 16 + kk];
        u64 xd0[4], xd1[4], xd2[4], xd3[4];
#pragma unroll
        for (int r = 0; r < 4; r++) {
            xd0[r] = pk2(xv[r].x, xv[r].x);
            xd1[r] = pk2(xv[r].y, xv[r].y);
            xd2[r] = pk2(xv[r].z, xv[r].z);
            xd3[r] = pk2(xv[r].w, xv[r].w);
        }
#pragma unroll
        for (int g2 = 0; g2 < 5; g2++) {
            const ulonglong2* wp =
                reinterpret_cast<const ulonglong2*>(&wq[g2 * 64 + kk * 4]);
            ulonglong2 wab = wp[0];   // k = 4kk, 4kk+1
            ulonglong2 wcd = wp[1];   // k = 4kk+2, 4kk+3
#pragma unroll
            for (int r = 0; r < 4; r++) {
                acc2[r][g2] = fma2(wab.x, xd0[r], acc2[r][g2]);
                acc2[r][g2] = fma2(wab.y, xd1[r], acc2[r][g2]);
                acc2[r][g2] = fma2(wcd.x, xd2[r], acc2[r][g2]);
                acc2[r][g2] = fma2(wcd.y, xd3[r], acc2[r][g2]);
            }
        }
    }
#pragma unroll
    for (int r = 0; r < 4; r++) {
        u64* o2 = reinterpret_cast<u64*>(d_XG1 + (r0 + r) * G4 + q * 10);
#pragma unroll
        for (int g2 = 0; g2 < 5; g2++) o2[g2] = acc2[r][g2];
    }
}

// ---------------------------------------------------------------------------
// Recurrence core. One warp per batch. Lane k (k = lane%10) owns unit k and
// computes ALL 4 of its gates via packed f32x2 ((i,f) and (g,o) pairs).
// Only one shfl stage (h broadcast) is on the critical path.
// ---------------------------------------------------------------------------
#define LSTM_STEP_CORE(abx, aby)                                              \
    {                                                                         \
        u64 eIF = fma2(wIF[0], hvp[0], (abx));                                \
        eIF = fma2(wIF[2], hvp[2], eIF);                                      \
        eIF = fma2(wIF[4], hvp[4], eIF);                                      \
        eIF = fma2(wIF[6], hvp[6], eIF);                                      \
        eIF = fma2(wIF[8], hvp[8], eIF);                                      \
        u64 oIF = mul2(wIF[1], hvp[1]);                                       \
        oIF = fma2(wIF[3], hvp[3], oIF);                                      \
        oIF = fma2(wIF[5], hvp[5], oIF);                                      \
        oIF = fma2(wIF[7], hvp[7], oIF);                                      \
        oIF = fma2(wIF[9], hvp[9], oIF);                                      \
        u64 gIF = add2(eIF, oIF);                                             \
        u64 eGO = fma2(wGO[0], hvp[0], (aby));                                \
        eGO = fma2(wGO[2], hvp[2], eGO);                                      \
        eGO = fma2(wGO[4], hvp[4], eGO);                                      \
        eGO = fma2(wGO[6], hvp[6], eGO);                                      \
        eGO = fma2(wGO[8], hvp[8], eGO);                                      \
        u64 oGO = mul2(wGO[1], hvp[1]);                                       \
        oGO = fma2(wGO[3], hvp[3], oGO);                                      \
        oGO = fma2(wGO[5], hvp[5], oGO);                                      \
        oGO = fma2(wGO[7], hvp[7], oGO);                                      \
        oGO = fma2(wGO[9], hvp[9], oGO);                                      \
        u64 gGO = add2(eGO, oGO);                                             \
        u64 sIF = mul2(gIF, cHH);   /* (gi/2, gf/2) */                        \
        u64 sGO = mul2(gGO, cOH);   /* (gg, go/2)  */                         \
        float xi, xf, xg, xo;                                                 \
        upk2(xi, xf, sIF);                                                    \
        upk2(xg, xo, sGO);                                                    \
        float ti = tanh_ap(xi);                                               \
        float tg = tanh_ap(xg);                                               \
        float tf = tanh_ap(xf);                                               \
        float to_ = tanh_ap(xo);                                              \
        float si = fmaf(ti, 0.5f, 0.5f);                                      \
        float sf = fmaf(tf, 0.5f, 0.5f);                                      \
        float so = fmaf(to_, 0.5f, 0.5f);                                     \
        c = fmaf(sf, c, si * tg);                                             \
        float tc = tanh_ap(c);                                                \
        h = so * tc;                                                          \
        _Pragma("unroll")                                                     \
        for (int j = 0; j < 10; j++) {                                        \
            float hj = __shfl_sync(0xffffffffu, h, j);                        \
            hvp[j] = pk2(hj, hj);                                             \
        }                                                                     \
    }

// lstm1: layer-1 recurrence + fused layer-2 input GEMM into d_XG2.
__global__ __launch_bounds__(256) void k_lstm1(
    const float* __restrict__ Whh,    // [40,10] layer-1 (orig order)
    const float* __restrict__ h0,
    const float* __restrict__ c0,
    const float* __restrict__ Wih2,   // [40,10]
    const float* __restrict__ bih2,
    const float* __restrict__ bhh2)
{
    int warp = (blockIdx.x * blockDim.x + threadIdx.x) >> 5;
    int lane = threadIdx.x & 31;
    int k = lane % HH;

    u64 wIF[10], wGO[10];
#pragma unroll
    for (int j = 0; j < 10; j++) {
        wIF[j] = pk2(Whh[(0 * HH + k) * HH + j], Whh[(1 * HH + k) * HH + j]);
        wGO[j] = pk2(Whh[(2 * HH + k) * HH + j], Whh[(3 * HH + k) * HH + j]);
    }
    // fused-gemm weights: lane l owns output positions (2l, 2l+1).
    int l2 = (lane < 20) ? lane : lane - 20;
    int u2 = l2 >> 1;
    int rA = (l2 & 1) ? (2 * HH + u2) : u2;   // i or g row
    int rB = rA + HH;                          // f or o row
    u64 w2p[10];
#pragma unroll
    for (int j = 0; j < 10; j++)
        w2p[j] = pk2(Wih2[rA * HH + j], Wih2[rB * HH + j]);
    u64 b2p = pk2(bih2[rA] + bhh2[rA], bih2[rB] + bhh2[rB]);

    u64 cHH = pk2(0.5f, 0.5f);
    u64 cOH = pk2(1.0f, 0.5f);

    float h = h0[warp * HH + k];
    float c = c0[warp * HH + k];
    u64 hvp[10];
#pragma unroll
    for (int j = 0; j < 10; j++) {
        float hj = __shfl_sync(0xffffffffu, h, j);
        hvp[j] = pk2(hj, hj);
    }

    const ulonglong2* base =
        reinterpret_cast<const ulonglong2*>(d_XG1) + (size_t)warp * TT * HH + k;
    u64* out2 = reinterpret_cast<u64*>(d_XG2) + (size_t)warp * TT * (G4 / 2) + lane;

    ulonglong2 cur[4], nxt[4];
#pragma unroll
    for (int i = 0; i < 4; i++) cur[i] = base[i * HH];
#pragma unroll
    for (int i = 0; i < 4; i++) nxt[i] = base[(4 + i) * HH];

    for (int t = 0; t < TT; t += 4) {
        ulonglong2 pf[4];
        if (t + 8 < TT) {
#pragma unroll
            for (int i = 0; i < 4; i++) pf[i] = base[(size_t)(t + 8 + i) * HH];
        }
#pragma unroll
        for (int s = 0; s < 4; s++) {
            LSTM_STEP_CORE(cur[s].x, cur[s].y);
            u64 acc = fma2(w2p[0], hvp[0], b2p);
            acc = fma2(w2p[1], hvp[1], acc);
            acc = fma2(w2p[2], hvp[2], acc);
            acc = fma2(w2p[3], hvp[3], acc);
            acc = fma2(w2p[4], hvp[4], acc);
            acc = fma2(w2p[5], hvp[5], acc);
            acc = fma2(w2p[6], hvp[6], acc);
            acc = fma2(w2p[7], hvp[7], acc);
            acc = fma2(w2p[8], hvp[8], acc);
            acc = fma2(w2p[9], hvp[9], acc);
            if (lane < 20) out2[(size_t)(t + s) * (G4 / 2)] = acc;
        }
#pragma unroll
        for (int i = 0; i < 4; i++) { cur[i] = nxt[i]; nxt[i] = pf[i]; }
    }
    if (lane < HH) {
        d_h1T[warp * HH + k] = h;
        d_c1T[warp * HH + k] = c;
    }
}

// lstm2: layer-2 recurrence + fused FC chain.
__global__ __launch_bounds__(256) void k_lstm2(
    const float* __restrict__ Whh,    // [40,10] layer-2
    const float* __restrict__ fc1w,
    const float* __restrict__ fc1b,
    const float* __restrict__ fc2w,   // [1024]
    const float* __restrict__ fc2b,
    float* __restrict__ out)
{
    int warp = (blockIdx.x * blockDim.x + threadIdx.x) >> 5;
    int lane = threadIdx.x & 31;
    int k = lane % HH;

    u64 wIF[10], wGO[10];
#pragma unroll
    for (int j = 0; j < 10; j++) {
        wIF[j] = pk2(Whh[(0 * HH + k) * HH + j], Whh[(1 * HH + k) * HH + j]);
        wGO[j] = pk2(Whh[(2 * HH + k) * HH + j], Whh[(3 * HH + k) * HH + j]);
    }
    u64 cHH = pk2(0.5f, 0.5f);
    u64 cOH = pk2(1.0f, 0.5f);

    float h = d_h1T[warp * HH + k];
    float c = d_c1T[warp * HH + k];
    u64 hvp[10];
#pragma unroll
    for (int j = 0; j < 10; j++) {
        float hj = __shfl_sync(0xffffffffu, h, j);
        hvp[j] = pk2(hj, hj);
    }

    const ulonglong2* base =
        reinterpret_cast<const ulonglong2*>(d_XG2) + (size_t)warp * TT * HH + k;
    const float4* f4 = reinterpret_cast<const float4*>(fc2w);

    ulonglong2 cur[4], nxt[4];
#pragma unroll
    for (int i = 0; i < 4; i++) cur[i] = base[i * HH];
#pragma unroll
    for (int i = 0; i < 4; i++) nxt[i] = base[(4 + i) * HH];

    float acc = 0.0f;   // sum_t h_k * fc2w[t]
    float s2 = 0.0f;    // sum_t fc2w[t]

    for (int t = 0; t < TT; t += 4) {
        ulonglong2 pf[4];
        if (t + 8 < TT) {
#pragma unroll
            for (int i = 0; i < 4; i++) pf[i] = base[(size_t)(t + 8 + i) * HH];
        }
        float4 fwv = __ldg(&f4[t >> 2]);
        float fw4[4] = {fwv.x, fwv.y, fwv.z, fwv.w};
#pragma unroll
        for (int s = 0; s < 4; s++) {
            LSTM_STEP_CORE(cur[s].x, cur[s].y);
            acc = fmaf(h, fw4[s], acc);
            s2 += fw4[s];
        }
#pragma unroll
        for (int i = 0; i < 4; i++) { cur[i] = nxt[i]; nxt[i] = pf[i]; }
    }

    float val = (lane < HH) ? acc * fc1w[k] : 0.0f;
#pragma unroll
    for (int off = 16; off > 0; off >>= 1)
        val += __shfl_xor_sync(0xffffffffu, val, off);
    if (lane == 0)
        out[warp] = val + fc1b[0] * s2 + fc2b[0];
}

// ---------------------------------------------------------------------------
extern "C" void kernel_launch(void* const* d_in, const int* in_sizes, int n_in,
                              void* d_out, int out_size)
{
    const float* x    = (const float*)d_in[0];
    const float* h0   = (const float*)d_in[1];
    const float* c0   = (const float*)d_in[2];
    const float* Wih1 = (const float*)d_in[3];
    const float* Whh1 = (const float*)d_in[4];
    const float* bih1 = (const float*)d_in[5];
    const float* bhh1 = (const float*)d_in[6];
    const float* Wih2 = (const float*)d_in[7];
    const float* Whh2 = (const float*)d_in[8];
    const float* bih2 = (const float*)d_in[9];
    const float* bhh2 = (const float*)d_in[10];
    const float* fc1w = (const float*)d_in[11];
    const float* fc1b = (const float*)d_in[12];
    const float* fc2w = (const float*)d_in[13];
    const float* fc2b = (const float*)d_in[14];
    float* out = (float*)d_out;

    k_inputgemm<<<2048, 256>>>(x, Wih1, bih1, bhh1);
    // 512 warps packed 8/block (2 per SMSP) so a second chain hides stalls
    k_lstm1<<<64, 256>>>(Whh1, h0, c0, Wih2, bih2, bhh2);
    k_lstm2<<<64, 256>>>(Whh2, fc1w, fc1b, fc2w, fc2b, out);
}